// round 2
// baseline (speedup 1.0000x reference)
#include <cuda_runtime.h>

#define B   256
#define T   2048
#define HID 128
#define ATT 8

#define SPLIT 16                   // CTAs per batch
#define CHUNK (T / SPLIT)          // 128 rows per CTA
#define NW 4                       // warps per CTA
#define THREADS (NW * 32)          // 128
#define ROWS_PER_WARP (CHUNK / NW) // 32
#define NB 8                       // rows per pipelined batch
#define NBATCH (ROWS_PER_WARP / NB)

__device__ float g_partial_v[B * SPLIT * HID];
__device__ float g_partial_s[B * SPLIT];

__global__ void __launch_bounds__(THREADS)
mata_pass1(const float* __restrict__ H,
           const float* __restrict__ mask,
           const float* __restrict__ Wt,
           const float* __restrict__ Wx,
           const float* __restrict__ rate,
           const float* __restrict__ obs_bias,
           const float* __restrict__ miss_bias,
           float* __restrict__ a_out)
{
    __shared__ __align__(16) float s_vred[NW][HID];
    __shared__ float s_sred[NW];

    const int bx   = blockIdx.x;
    const int b    = bx / SPLIT;
    const int c    = bx % SPLIT;
    const int tid  = threadIdx.x;
    const int wid  = tid >> 5;
    const int lane = tid & 31;

    const float* Hb = H + (size_t)b * T * HID;

    // ---- every warp redundantly computes q then its own pv slice (no syncthreads) ----
    const float4 hlast = __ldg((const float4*)(Hb + (size_t)(T - 1) * HID) + lane);
    const int h0 = lane * 4;
    float qa[ATT];
    #pragma unroll
    for (int a = 0; a < ATT; a++) {
        float v = hlast.x * __ldg(Wt + (h0 + 0) * ATT + a)
                + hlast.y * __ldg(Wt + (h0 + 1) * ATT + a)
                + hlast.z * __ldg(Wt + (h0 + 2) * ATT + a)
                + hlast.w * __ldg(Wt + (h0 + 3) * ATT + a);
        #pragma unroll
        for (int off = 16; off > 0; off >>= 1)
            v += __shfl_xor_sync(0xffffffffu, v, off);
        qa[a] = v;   // every lane now has the full q[a]
    }
    float4 pv = make_float4(0.f, 0.f, 0.f, 0.f);
    #pragma unroll
    for (int a = 0; a < ATT; a++) {
        pv.x += qa[a] * __ldg(Wx + (h0 + 0) * ATT + a);
        pv.y += qa[a] * __ldg(Wx + (h0 + 1) * ATT + a);
        pv.z += qa[a] * __ldg(Wx + (h0 + 2) * ATT + a);
        pv.w += qa[a] * __ldg(Wx + (h0 + 3) * ATT + a);
    }

    const float sr = 1.f / (1.f + __expf(-__ldg(rate)));
    const float ob = __ldg(obs_bias);
    const float mb = __ldg(miss_bias);

    const int t0 = c * CHUNK + wid * ROWS_PER_WARP;
    const float* __restrict__ mrow = mask + (size_t)b * T;
    float* __restrict__ arow = a_out + (size_t)b * T;

    float4 acc  = make_float4(0.f, 0.f, 0.f, 0.f);
    float  sumw = 0.f;

    // ---- software-pipelined main loop: batches of 8 rows, prefetch next 8 ----
    float4 cur[NB];
    #pragma unroll
    for (int j = 0; j < NB; j++)
        cur[j] = __ldg((const float4*)(Hb + (size_t)(t0 + j) * HID) + lane);

    #pragma unroll
    for (int kb = 0; kb < NBATCH; kb++) {
        float4 nxt[NB];
        if (kb + 1 < NBATCH) {
            #pragma unroll
            for (int j = 0; j < NB; j++)
                nxt[j] = __ldg((const float4*)(Hb + (size_t)(t0 + (kb + 1) * NB + j) * HID) + lane);
        }

        // 8 independent dot products
        float d[NB];
        #pragma unroll
        for (int j = 0; j < NB; j++)
            d[j] = cur[j].x * pv.x + cur[j].y * pv.y + cur[j].z * pv.z + cur[j].w * pv.w;

        // interleaved butterfly — 8 independent reduction chains pipeline through SHFL
        #pragma unroll
        for (int off = 16; off > 0; off >>= 1) {
            #pragma unroll
            for (int j = 0; j < NB; j++)
                d[j] += __shfl_xor_sync(0xffffffffu, d[j], off);
        }

        float w[NB];
        #pragma unroll
        for (int j = 0; j < NB; j++) {
            const int t = t0 + kb * NB + j;
            const float s   = 1.f / (1.f + __expf(-d[j]));
            const float bt  = (float)(T - t);
            const float den = sr * (__logf(2.72f + (1.f - s)) * bt);
            const float e   = fmaxf(s / den, 0.f);
            const float m   = __ldg(mrow + t);
            w[j] = __expf(e + (m > 0.5f ? ob : mb));
            acc.x += w[j] * cur[j].x; acc.y += w[j] * cur[j].y;
            acc.z += w[j] * cur[j].z; acc.w += w[j] * cur[j].w;
            sumw  += w[j];
        }

        // all lanes hold all w[j]; lanes 0..7 store unnormalized weights
        float wl = w[0];
        #pragma unroll
        for (int j = 1; j < NB; j++) if (lane == j) wl = w[j];
        if (lane < NB) arow[t0 + kb * NB + lane] = wl;

        #pragma unroll
        for (int j = 0; j < NB; j++) cur[j] = nxt[j];
    }

    // ---- CTA reduce partial v / sumw ----
    ((float4*)&s_vred[wid][0])[lane] = acc;
    if (lane == 0) s_sred[wid] = sumw;
    __syncthreads();

    if (tid < HID) {
        float v = 0.f;
        #pragma unroll
        for (int w = 0; w < NW; w++) v += s_vred[w][tid];
        g_partial_v[((size_t)b * SPLIT + c) * HID + tid] = v;
    }
    if (tid == 0) {
        float ss = 0.f;
        #pragma unroll
        for (int w = 0; w < NW; w++) ss += s_sred[w];
        g_partial_s[b * SPLIT + c] = ss;
    }
}

__global__ void __launch_bounds__(256)
mata_pass2(float* __restrict__ v_out, float* __restrict__ a_out)
{
    const int b   = blockIdx.x;
    const int tid = threadIdx.x;
    __shared__ float s_inv;

    if (tid == 0) {
        float ss = 0.f;
        #pragma unroll
        for (int cc = 0; cc < SPLIT; cc++) ss += g_partial_s[b * SPLIT + cc];
        s_inv = 1.f / ss;
    }
    __syncthreads();
    const float inv = s_inv;

    if (tid < HID) {
        float v = 0.f;
        #pragma unroll
        for (int cc = 0; cc < SPLIT; cc++)
            v += g_partial_v[((size_t)b * SPLIT + cc) * HID + tid];
        v_out[(size_t)b * HID + tid] = v * inv;
    }

    float4* ab4 = (float4*)(a_out + (size_t)b * T);
    #pragma unroll
    for (int i = tid; i < T / 4; i += 256) {
        float4 x = ab4[i];
        x.x *= inv; x.y *= inv; x.z *= inv; x.w *= inv;
        ab4[i] = x;
    }
}

extern "C" void kernel_launch(void* const* d_in, const int* in_sizes, int n_in,
                              void* d_out, int out_size)
{
    const float* H   = (const float*)d_in[0];
    const float* msk = (const float*)d_in[1];
    const float* Wt  = (const float*)d_in[2];
    const float* Wx  = (const float*)d_in[3];
    const float* rt  = (const float*)d_in[4];
    const float* ob  = (const float*)d_in[5];
    const float* mb  = (const float*)d_in[6];

    float* v_out = (float*)d_out;               // [B, HID]
    float* a_out = (float*)d_out + B * HID;     // [B, T]

    mata_pass1<<<B * SPLIT, THREADS>>>(H, msk, Wt, Wx, rt, ob, mb, a_out);
    mata_pass2<<<B, 256>>>(v_out, a_out);
}

// round 3
// speedup vs baseline: 2.7465x; 2.7465x over previous
#include <cuda_runtime.h>
#include <cstdint>

#define B   256
#define T   2048
#define HID 128
#define ATT 8

#define SPLIT 4                    // CTAs per batch
#define CHUNK (T / SPLIT)          // 512 rows per CTA
#define NW 4                       // warps per CTA
#define THREADS (NW * 32)
#define ROWS_PER_WARP (CHUNK / NW) // 128
#define TR 8                       // rows per tile
#define NTILES (ROWS_PER_WARP / TR)// 16
#define TILE_F4 (TR * 32)          // 256 float4 per tile

__device__ float g_partial_v[B * SPLIT * HID];
__device__ float g_partial_s[B * SPLIT];

__device__ __forceinline__ void cp_async16(uint32_t dst, const void* src) {
    asm volatile("cp.async.cg.shared.global [%0], [%1], 16;\n" :: "r"(dst), "l"(src));
}
__device__ __forceinline__ void cp_commit() {
    asm volatile("cp.async.commit_group;\n" ::: "memory");
}
template<int N> __device__ __forceinline__ void cp_wait() {
    asm volatile("cp.async.wait_group %0;\n" :: "n"(N) : "memory");
}
__device__ __forceinline__ uint32_t smem_u32(const void* p) {
    return (uint32_t)__cvta_generic_to_shared(p);
}

// swizzled float4 index within a tile: row j, logical float4 f
__device__ __forceinline__ int swz(int j, int f) {
    return j * 32 + (f ^ (j & 7) ^ ((f >> 3) & 7));
}

__global__ void __launch_bounds__(THREADS)
mata_pass1(const float* __restrict__ H,
           const float* __restrict__ mask,
           const float* __restrict__ Wt,
           const float* __restrict__ Wx,
           const float* __restrict__ rate,
           const float* __restrict__ obs_bias,
           const float* __restrict__ miss_bias,
           float* __restrict__ a_out)
{
    __shared__ __align__(16) float4 s_tile[NW * 2 * TILE_F4];   // 32 KB
    __shared__ __align__(16) float  s_pp[3 * 164 + 128 + 4];    // 4 bank-offset copies of p
    __shared__ float s_w[NW][TR];
    __shared__ __align__(16) float s_vred[NW][HID];
    __shared__ float s_sred[NW];

    const int bx   = blockIdx.x;
    const int b    = bx / SPLIT;
    const int c    = bx % SPLIT;
    const int tid  = threadIdx.x;
    const int wid  = tid >> 5;
    const int lane = tid & 31;

    const float* Hb = H + (size_t)b * T * HID;
    const int t0w = c * CHUNK + wid * ROWS_PER_WARP;

    float4* mybuf = s_tile + wid * 2 * TILE_F4;
    const uint32_t mybuf_u = smem_u32(mybuf);

    // ---- producer: issue tiles 0 and 1 (double-buffer prologue) ----
    #pragma unroll
    for (int kt = 0; kt < 2; kt++) {
        const float4* src = (const float4*)(Hb + (size_t)(t0w + kt * TR) * HID);
        const uint32_t dbase = mybuf_u + kt * TILE_F4 * 16;
        #pragma unroll
        for (int j = 0; j < TR; j++)
            cp_async16(dbase + swz(j, lane) * 16, src + j * 32 + lane);
        cp_commit();
    }

    // ---- warp 0 computes q then p (4 bank-offset copies in smem) ----
    if (wid == 0) {
        const float4 hlast = __ldg((const float4*)(Hb + (size_t)(T - 1) * HID) + lane);
        const int h0 = lane * 4;
        float qa[ATT];
        #pragma unroll
        for (int a = 0; a < ATT; a++) {
            float v = hlast.x * __ldg(Wt + (h0 + 0) * ATT + a)
                    + hlast.y * __ldg(Wt + (h0 + 1) * ATT + a)
                    + hlast.z * __ldg(Wt + (h0 + 2) * ATT + a)
                    + hlast.w * __ldg(Wt + (h0 + 3) * ATT + a);
            #pragma unroll
            for (int off = 16; off > 0; off >>= 1)
                v += __shfl_xor_sync(0xffffffffu, v, off);
            qa[a] = v;
        }
        float4 pv = make_float4(0.f, 0.f, 0.f, 0.f);
        #pragma unroll
        for (int a = 0; a < ATT; a++) {
            pv.x += qa[a] * __ldg(Wx + (h0 + 0) * ATT + a);
            pv.y += qa[a] * __ldg(Wx + (h0 + 1) * ATT + a);
            pv.z += qa[a] * __ldg(Wx + (h0 + 2) * ATT + a);
            pv.w += qa[a] * __ldg(Wx + (h0 + 3) * ATT + a);
        }
        #pragma unroll
        for (int cp = 0; cp < 4; cp++) {
            s_pp[cp * 164 + h0 + 0] = pv.x;
            s_pp[cp * 164 + h0 + 1] = pv.y;
            s_pp[cp * 164 + h0 + 2] = pv.z;
            s_pp[cp * 164 + h0 + 3] = pv.w;
        }
    }

    const float sr = 1.f / (1.f + __expf(-__ldg(rate)));
    const float ob = __ldg(obs_bias);
    const float mb = __ldg(miss_bias);

    __syncthreads();   // p visible to all warps

    const float* __restrict__ mrow = mask + (size_t)b * T;
    float* __restrict__ arow = a_out + (size_t)b * T;

    const int r  = lane & 7;       // row within tile (phase A)
    const int qq = lane >> 3;      // quarter-row (phase A)

    float4 acc  = make_float4(0.f, 0.f, 0.f, 0.f);
    float  sumw = 0.f;

    #pragma unroll 1
    for (int kt = 0; kt < NTILES; kt++) {
        if (kt < NTILES - 1) cp_wait<1>(); else cp_wait<0>();
        __syncwarp();

        const float4* buf = mybuf + (kt & 1) * TILE_F4;
        const int tbase = t0w + kt * TR;

        // mask prefetch (independent of tile data)
        const float m = __ldg(mrow + tbase + r);

        // ---- phase A: dot(H_row, p), 4 lanes per row ----
        float d = 0.f;
        #pragma unroll
        for (int i = 0; i < 8; i++) {
            const int f = qq * 8 + i;
            const float4 tv = buf[swz(r, f)];
            const float4 pp = *(const float4*)(s_pp + qq * 196 + 4 * i);
            d += tv.x * pp.x + tv.y * pp.y + tv.z * pp.z + tv.w * pp.w;
        }
        d += __shfl_xor_sync(0xffffffffu, d, 8);
        d += __shfl_xor_sync(0xffffffffu, d, 16);

        // ---- per-row weight (all rows in parallel across lanes) ----
        const int t = tbase + r;
        const float s   = 1.f / (1.f + __expf(-d));
        const float bt  = (float)(T - t);
        const float den = sr * (__logf(2.72f + (1.f - s)) * bt);
        const float e   = fmaxf(s / den, 0.f);
        const float w   = __expf(e + (m > 0.5f ? ob : mb));

        if (qq == 0) { s_w[wid][r] = w; arow[t] = w; }
        __syncwarp();

        // ---- phase B: acc[h] += w[row] * H[row][h] ----
        #pragma unroll
        for (int r2 = 0; r2 < TR; r2++) {
            const float wr = s_w[wid][r2];
            const float4 tv = buf[swz(r2, lane)];
            acc.x += wr * tv.x; acc.y += wr * tv.y;
            acc.z += wr * tv.z; acc.w += wr * tv.w;
            sumw += wr;
        }
        __syncwarp();

        // ---- producer: refill this buffer with tile kt+2 ----
        if (kt + 2 < NTILES) {
            const float4* src = (const float4*)(Hb + (size_t)(t0w + (kt + 2) * TR) * HID);
            const uint32_t dbase = mybuf_u + (kt & 1) * TILE_F4 * 16;
            #pragma unroll
            for (int j = 0; j < TR; j++)
                cp_async16(dbase + swz(j, lane) * 16, src + j * 32 + lane);
            cp_commit();
        }
    }

    // ---- CTA reduction ----
    ((float4*)&s_vred[wid][0])[lane] = acc;
    if (lane == 0) s_sred[wid] = sumw;
    __syncthreads();

    if (tid < HID) {
        float v = 0.f;
        #pragma unroll
        for (int w = 0; w < NW; w++) v += s_vred[w][tid];
        g_partial_v[((size_t)b * SPLIT + c) * HID + tid] = v;
    }
    if (tid == 0) {
        float ss = 0.f;
        #pragma unroll
        for (int w = 0; w < NW; w++) ss += s_sred[w];
        g_partial_s[b * SPLIT + c] = ss;
    }
}

__global__ void __launch_bounds__(256)
mata_pass2(float* __restrict__ v_out, float* __restrict__ a_out)
{
    const int b    = blockIdx.x >> 1;
    const int half = blockIdx.x & 1;
    const int tid  = threadIdx.x;

    float ss = 0.f;
    #pragma unroll
    for (int cc = 0; cc < SPLIT; cc++) ss += g_partial_s[b * SPLIT + cc];
    const float inv = 1.f / ss;

    if (half == 0 && tid < HID) {
        float v = 0.f;
        #pragma unroll
        for (int cc = 0; cc < SPLIT; cc++)
            v += g_partial_v[((size_t)b * SPLIT + cc) * HID + tid];
        v_out[(size_t)b * HID + tid] = v * inv;
    }

    // each thread normalizes exactly one float4 of a
    float4* ab4 = (float4*)(a_out + (size_t)b * T);
    const int i = half * 256 + tid;
    float4 x = ab4[i];
    x.x *= inv; x.y *= inv; x.z *= inv; x.w *= inv;
    ab4[i] = x;
}

extern "C" void kernel_launch(void* const* d_in, const int* in_sizes, int n_in,
                              void* d_out, int out_size)
{
    const float* H   = (const float*)d_in[0];
    const float* msk = (const float*)d_in[1];
    const float* Wt  = (const float*)d_in[2];
    const float* Wx  = (const float*)d_in[3];
    const float* rt  = (const float*)d_in[4];
    const float* ob  = (const float*)d_in[5];
    const float* mb  = (const float*)d_in[6];

    float* v_out = (float*)d_out;               // [B, HID]
    float* a_out = (float*)d_out + B * HID;     // [B, T]

    mata_pass1<<<B * SPLIT, THREADS>>>(H, msk, Wt, Wx, rt, ob, mb, a_out);
    mata_pass2<<<B * 2, 256>>>(v_out, a_out);
}

// round 4
// speedup vs baseline: 2.8335x; 1.0317x over previous
#include <cuda_runtime.h>
#include <cstdint>

#define B   256
#define T   2048
#define HID 128
#define ATT 8

#define SPLIT 2                    // CTAs per batch
#define CHUNK (T / SPLIT)          // 1024 rows per CTA
#define NW 4                       // warps per CTA
#define THREADS (NW * 32)
#define ROWS_PER_WARP (CHUNK / NW) // 256
#define TR 8                       // rows per tile
#define NTILES (ROWS_PER_WARP / TR)// 32
#define TILE_F4 (TR * 32)          // 256 float4 per tile (4 KB)
#define NSTAGE 3

__device__ float g_partial_v[B * SPLIT * HID];
__device__ float g_partial_s[B * SPLIT];

__device__ __forceinline__ void cp_async16(uint32_t dst, const void* src) {
    asm volatile("cp.async.cg.shared.global [%0], [%1], 16;\n"
                 :: "r"(dst), "l"(src) : "memory");
}
__device__ __forceinline__ void cp_commit() {
    asm volatile("cp.async.commit_group;\n" ::: "memory");
}
template<int N> __device__ __forceinline__ void cp_wait() {
    asm volatile("cp.async.wait_group %0;\n" :: "n"(N) : "memory");
}
__device__ __forceinline__ uint32_t smem_u32(const void* p) {
    return (uint32_t)__cvta_generic_to_shared(p);
}

#define FULL 0xffffffffu

__global__ void __launch_bounds__(THREADS)
mata_pass1(const float* __restrict__ H,
           const float* __restrict__ mask,
           const float* __restrict__ Wt,
           const float* __restrict__ Wx,
           const float* __restrict__ rate,
           const float* __restrict__ obs_bias,
           const float* __restrict__ miss_bias,
           float* __restrict__ a_out)
{
    __shared__ __align__(16) float4 s_tile[NW * NSTAGE * TILE_F4];  // 48 KB
    __shared__ __align__(16) float  s_vred[NW][HID];
    __shared__ float s_sred[NW];

    const int bx   = blockIdx.x;
    const int b    = bx / SPLIT;
    const int c    = bx % SPLIT;
    const int tid  = threadIdx.x;
    const int wid  = tid >> 5;
    const int lane = tid & 31;

    const float* Hb = H + (size_t)b * T * HID;
    const int t0w = c * CHUNK + wid * ROWS_PER_WARP;

    float4* mybuf = s_tile + wid * NSTAGE * TILE_F4;
    const uint32_t mybuf_u = smem_u32(mybuf);

    // ---- prologue: prefetch tiles 0..2 (one commit group each) ----
    #pragma unroll
    for (int p = 0; p < NSTAGE; p++) {
        const float4* src = (const float4*)(Hb + (size_t)(t0w + p * TR) * HID);
        const uint32_t dbase = mybuf_u + p * TILE_F4 * 16;
        #pragma unroll
        for (int j = 0; j < TR; j++)
            cp_async16(dbase + (j * 32 + lane) * 16, src + j * 32 + lane);
        cp_commit();
    }

    // ---- every warp redundantly computes q, then its own slice of p ----
    const float4 hlast = __ldg((const float4*)(Hb + (size_t)(T - 1) * HID) + lane);
    const int h0 = lane * 4;
    float qa[ATT];
    #pragma unroll
    for (int a = 0; a < ATT; a++) {
        float v = hlast.x * __ldg(Wt + (h0 + 0) * ATT + a)
                + hlast.y * __ldg(Wt + (h0 + 1) * ATT + a)
                + hlast.z * __ldg(Wt + (h0 + 2) * ATT + a)
                + hlast.w * __ldg(Wt + (h0 + 3) * ATT + a);
        #pragma unroll
        for (int off = 16; off > 0; off >>= 1)
            v += __shfl_xor_sync(FULL, v, off);
        qa[a] = v;
    }
    float4 pv = make_float4(0.f, 0.f, 0.f, 0.f);
    #pragma unroll
    for (int a = 0; a < ATT; a++) {
        pv.x += qa[a] * __ldg(Wx + (h0 + 0) * ATT + a);
        pv.y += qa[a] * __ldg(Wx + (h0 + 1) * ATT + a);
        pv.z += qa[a] * __ldg(Wx + (h0 + 2) * ATT + a);
        pv.w += qa[a] * __ldg(Wx + (h0 + 3) * ATT + a);
    }

    const float sr = 1.f / (1.f + __expf(-__ldg(rate)));
    const float ob = __ldg(obs_bias);
    const float mb = __ldg(miss_bias);

    const float* __restrict__ mrow = mask + (size_t)b * T;
    float* __restrict__ arow = a_out + (size_t)b * T;

    const int vrow = (lane >> 2) & 7;   // row this lane-group owns post-reduce

    float4 acc  = make_float4(0.f, 0.f, 0.f, 0.f);
    float  sumw = 0.f;
    int slot = 0;

    #pragma unroll 1
    for (int kt = 0; kt < NTILES; kt++) {
        const int tbase = t0w + kt * TR;

        // mask prefetch (covered by reduce latency)
        const float m = __ldg(mrow + tbase + vrow);

        cp_wait<2>();   // tile kt resident

        const float4* buf = mybuf + slot * TILE_F4;

        // single smem read of the tile: lane holds column `lane` of all 8 rows
        float4 tv[TR];
        #pragma unroll
        for (int j = 0; j < TR; j++) tv[j] = buf[j * 32 + lane];

        // partial dots (also pins the LDS before the refill below)
        float d[TR];
        #pragma unroll
        for (int j = 0; j < TR; j++)
            d[j] = tv[j].x * pv.x + tv[j].y * pv.y + tv[j].z * pv.z + tv[j].w * pv.w;

        // refill this slot with tile kt+3
        if (kt + NSTAGE < NTILES) {
            const float4* src = (const float4*)(Hb + (size_t)(t0w + (kt + NSTAGE) * TR) * HID);
            const uint32_t dbase = mybuf_u + slot * TILE_F4 * 16;
            #pragma unroll
            for (int j = 0; j < TR; j++)
                cp_async16(dbase + (j * 32 + lane) * 16, src + j * 32 + lane);
            cp_commit();
        }

        // ---- value-halving cross-lane reduction: 9 shuffles ----
        const bool hi16 = (lane & 16) != 0;
        float e[4];
        #pragma unroll
        for (int j = 0; j < 4; j++) {
            float x = hi16 ? d[j] : d[j + 4];
            float r = __shfl_xor_sync(FULL, x, 16);
            e[j] = (hi16 ? d[j + 4] : d[j]) + r;
        }
        const bool hi8 = (lane & 8) != 0;
        float f[2];
        #pragma unroll
        for (int j = 0; j < 2; j++) {
            float x = hi8 ? e[j] : e[j + 2];
            float r = __shfl_xor_sync(FULL, x, 8);
            f[j] = (hi8 ? e[j + 2] : e[j]) + r;
        }
        const bool hi4 = (lane & 4) != 0;
        {
            float x = hi4 ? f[0] : f[1];
            float r = __shfl_xor_sync(FULL, x, 4);
            f[0] = (hi4 ? f[1] : f[0]) + r;
        }
        f[0] += __shfl_xor_sync(FULL, f[0], 1);
        f[0] += __shfl_xor_sync(FULL, f[0], 2);
        // f[0] = full dot of row `vrow`

        // ---- weight for owned row (lane-parallel MUFU) ----
        const int t = tbase + vrow;
        const float s   = 1.f / (1.f + __expf(-f[0]));
        const float bt  = (float)(T - t);
        const float den = sr * (__logf(2.72f + (1.f - s)) * bt);
        const float e2  = fmaxf(s / den, 0.f);
        const float w   = __expf(e2 + (m > 0.5f ? ob : mb));

        if ((lane & 3) == 0) arow[t] = w;   // 8 lanes, consecutive t -> coalesced 32B

        // broadcast all 8 weights, accumulate from registers
        #pragma unroll
        for (int r2 = 0; r2 < TR; r2++) {
            const float wr = __shfl_sync(FULL, w, r2 << 2);
            acc.x += wr * tv[r2].x; acc.y += wr * tv[r2].y;
            acc.z += wr * tv[r2].z; acc.w += wr * tv[r2].w;
            sumw  += wr;
        }

        slot = (slot == NSTAGE - 1) ? 0 : slot + 1;
    }

    // ---- CTA reduction ----
    ((float4*)&s_vred[wid][0])[lane] = acc;
    if (lane == 0) s_sred[wid] = sumw;
    __syncthreads();

    if (tid < HID) {
        float v = 0.f;
        #pragma unroll
        for (int w = 0; w < NW; w++) v += s_vred[w][tid];
        g_partial_v[((size_t)b * SPLIT + c) * HID + tid] = v;
    }
    if (tid == 0) {
        float ss = 0.f;
        #pragma unroll
        for (int w = 0; w < NW; w++) ss += s_sred[w];
        g_partial_s[b * SPLIT + c] = ss;
    }
}

__global__ void __launch_bounds__(256)
mata_pass2(float* __restrict__ v_out, float* __restrict__ a_out)
{
    const int b    = blockIdx.x >> 1;
    const int half = blockIdx.x & 1;
    const int tid  = threadIdx.x;

    float ss = 0.f;
    #pragma unroll
    for (int cc = 0; cc < SPLIT; cc++) ss += g_partial_s[b * SPLIT + cc];
    const float inv = 1.f / ss;

    if (half == 0 && tid < HID) {
        float v = 0.f;
        #pragma unroll
        for (int cc = 0; cc < SPLIT; cc++)
            v += g_partial_v[((size_t)b * SPLIT + cc) * HID + tid];
        v_out[(size_t)b * HID + tid] = v * inv;
    }

    float4* ab4 = (float4*)(a_out + (size_t)b * T);
    const int i = half * 256 + tid;
    float4 x = ab4[i];
    x.x *= inv; x.y *= inv; x.z *= inv; x.w *= inv;
    ab4[i] = x;
}

extern "C" void kernel_launch(void* const* d_in, const int* in_sizes, int n_in,
                              void* d_out, int out_size)
{
    const float* H   = (const float*)d_in[0];
    const float* msk = (const float*)d_in[1];
    const float* Wt  = (const float*)d_in[2];
    const float* Wx  = (const float*)d_in[3];
    const float* rt  = (const float*)d_in[4];
    const float* ob  = (const float*)d_in[5];
    const float* mb  = (const float*)d_in[6];

    float* v_out = (float*)d_out;               // [B, HID]
    float* a_out = (float*)d_out + B * HID;     // [B, T]

    mata_pass1<<<B * SPLIT, THREADS>>>(H, msk, Wt, Wx, rt, ob, mb, a_out);
    mata_pass2<<<B * 2, 256>>>(v_out, a_out);
}